// round 9
// baseline (speedup 1.0000x reference)
#include <cuda_runtime.h>
#include <cuda_bf16.h>
#include <cuda_fp16.h>

#define N_NODES 50000
#define N_EDGES 800000
#define IN_DIM  256
#define HID     128
#define OUT_DIM 3
#define EDGE_DIM 4
#define N_LAYERS 4

// ---------------- static device scratch (no allocations allowed) -------------
__device__ float  g_x  [N_NODES * HID];
__device__ __half g_P1h[N_NODES * HID];     // x @ W1 in fp16 (gathered by edges)
__device__ float  g_P2 [N_NODES * HID];     // x @ W2 + b_msg
__device__ int    g_deg[N_NODES];
__device__ int    g_rank[N_EDGES];          // edge rank within its dst bucket
__device__ int    g_off[N_NODES + 1];
__device__ int    g_csr_src[N_EDGES];
__device__ float4 g_csr_ea [N_EDGES];
// Precomputed fp16 B fragments in per-lane mma order:
//   layer weights: [layer(4)][target(2)][n8(16)][kg(8)][lane(32)] uint2
//   input weights: [n8(16)][kg(16)][lane(32)] uint2
__device__ uint2  g_Bfrag  [N_LAYERS * 2 * 16 * 8 * 32];
__device__ uint2  g_BfragIn[16 * 16 * 32];

// ---------------- CSR build + weight prep (merged kernel) --------------------
__global__ void count_prep_kernel(const int* __restrict__ ei,
                                  const float* __restrict__ W_in,
                                  const float* __restrict__ W_msg) {
    int gid = blockIdx.x * blockDim.x + threadIdx.x;
    if (gid < N_EDGES) {
        int dst = ei[N_EDGES + gid];
        g_rank[gid] = atomicAdd(&g_deg[dst], 1);   // rank doubles as fill position
    }
    // ---- independent: B-fragment precompute (low gids only) ----
    int lane = gid & 31;
    int rest = gid >> 5;
    const int NLAYER_ELEMS = N_LAYERS * 2 * 16 * 8;   // 1024 warp-slots
    if (rest < NLAYER_ELEMS) {
        int kg  = rest & 7;
        int n8  = (rest >> 3) & 15;
        int tgt = (rest >> 7) & 1;
        int l   = rest >> 8;
        const float* W = W_msg + (size_t)l * (2 * HID + EDGE_DIM) * HID
                               + (size_t)tgt * HID * HID;
        int n  = n8 * 8 + (lane >> 2);
        int k0 = kg * 16 + (lane & 3) * 2;
        __half2 b0 = __floats2half2_rn(W[(size_t)k0 * HID + n],
                                       W[(size_t)(k0 + 1) * HID + n]);
        __half2 b1 = __floats2half2_rn(W[(size_t)(k0 + 8) * HID + n],
                                       W[(size_t)(k0 + 9) * HID + n]);
        uint2 v;
        v.x = *(unsigned*)&b0;
        v.y = *(unsigned*)&b1;
        g_Bfrag[(size_t)rest * 32 + lane] = v;
    } else if (rest < NLAYER_ELEMS + 16 * 16) {
        int r2 = rest - NLAYER_ELEMS;
        int kg = r2 & 15;
        int n8 = r2 >> 4;
        int n  = n8 * 8 + (lane >> 2);
        int k0 = kg * 16 + (lane & 3) * 2;
        __half2 b0 = __floats2half2_rn(W_in[(size_t)k0 * HID + n],
                                       W_in[(size_t)(k0 + 1) * HID + n]);
        __half2 b1 = __floats2half2_rn(W_in[(size_t)(k0 + 8) * HID + n],
                                       W_in[(size_t)(k0 + 9) * HID + n]);
        uint2 v;
        v.x = *(unsigned*)&b0;
        v.y = *(unsigned*)&b1;
        g_BfragIn[(size_t)r2 * 32 + lane] = v;
    }
}

// single-block exclusive scan over g_deg -> g_off (proven in R1-R3)
__global__ __launch_bounds__(1024)
void scan_deg_kernel() {
    __shared__ int warp_sums[32];
    __shared__ int s_carry;
    int tid  = threadIdx.x;
    int lane = tid & 31;
    int wid  = tid >> 5;
    if (tid == 0) s_carry = 0;
    __syncthreads();

    for (int base = 0; base < N_NODES; base += 1024) {
        int v = base + tid;
        int d = (v < N_NODES) ? g_deg[v] : 0;
        int x = d;
        #pragma unroll
        for (int o = 1; o < 32; o <<= 1) {
            int y = __shfl_up_sync(0xFFFFFFFFu, x, o);
            if (lane >= o) x += y;
        }
        if (lane == 31) warp_sums[wid] = x;
        __syncthreads();
        if (wid == 0) {
            int w = warp_sums[lane];
            #pragma unroll
            for (int o = 1; o < 32; o <<= 1) {
                int y = __shfl_up_sync(0xFFFFFFFFu, w, o);
                if (lane >= o) w += y;
            }
            warp_sums[lane] = w;
        }
        __syncthreads();
        int prefix = (wid > 0) ? warp_sums[wid - 1] : 0;
        int incl   = x + prefix;
        int carry  = s_carry;
        if (v < N_NODES) g_off[v] = carry + incl - d;
        int total = warp_sums[31];
        __syncthreads();
        if (tid == 0) s_carry = carry + total;
        __syncthreads();
    }
    if (tid == 0) g_off[N_NODES] = N_EDGES;
}

__global__ void fill_csr_kernel(const int* __restrict__ ei,
                                const float* __restrict__ ea) {
    int e = blockIdx.x * blockDim.x + threadIdx.x;
    if (e >= N_EDGES) return;
    int src = ei[e];
    int dst = ei[N_EDGES + e];
    int pos = g_off[dst] + g_rank[e];      // atomic-free
    g_csr_src[pos] = src;
    g_csr_ea[pos]  = *(const float4*)(ea + (size_t)e * 4);
}

// ---------------- MMA helpers -------------------------------------------------
#define MMA_F16(c, a, b)                                                        \
    asm volatile(                                                               \
        "mma.sync.aligned.m16n8k16.row.col.f32.f16.f16.f32 "                    \
        "{%0,%1,%2,%3}, {%4,%5,%6,%7}, {%8,%9}, {%0,%1,%2,%3};\n"               \
        : "+f"((c)[0]), "+f"((c)[1]), "+f"((c)[2]), "+f"((c)[3])                \
        : "r"((a)[0]), "r"((a)[1]), "r"((a)[2]), "r"((a)[3]),                   \
          "r"((b)[0]), "r"((b)[1]))

__device__ __forceinline__ unsigned f2h2(float a, float b) {
    __half2 h = __floats2half2_rn(a, b);
    return *(unsigned*)&h;
}

// load one A fragment (4 regs) for mma.m16n8k16 directly from fp32 global
__device__ __forceinline__ void loadAfrag(unsigned a[4], const float* __restrict__ A,
                                          int r, int kc, int K, int M) {
    const float* Ar = A + (size_t)r * K + kc;
    bool ok0 = r < M, ok1 = (r + 8) < M;
    float2 v0 = ok0 ? *(const float2*)(Ar)             : make_float2(0.f, 0.f);
    float2 v1 = ok1 ? *(const float2*)(Ar + 8 * K)     : make_float2(0.f, 0.f);
    float2 v2 = ok0 ? *(const float2*)(Ar + 8)         : make_float2(0.f, 0.f);
    float2 v3 = ok1 ? *(const float2*)(Ar + 8 * K + 8) : make_float2(0.f, 0.f);
    a[0] = f2h2(v0.x, v0.y);
    a[1] = f2h2(v1.x, v1.y);
    a[2] = f2h2(v2.x, v2.y);
    a[3] = f2h2(v3.x, v3.y);
}

// ---------------- input projection GEMM (K=256), register-direct -------------
#define GBM 128

__global__ __launch_bounds__(256, 2)
void gemm_in_reg_kernel(const float* __restrict__ A,
                        const float* __restrict__ bias0,
                        float* __restrict__ C0, int M) {
    int tid  = threadIdx.x;
    int lane = tid & 31;
    int warp = tid >> 5;
    int warpM = warp >> 1;
    int warpN = warp & 1;
    int rowBase = blockIdx.x * GBM;

    float c[2][8][4] = {};

    #pragma unroll
    for (int kg = 0; kg < 16; ++kg) {
        int kc = kg * 16 + (lane & 3) * 2;
        unsigned a[2][4];
        #pragma unroll
        for (int m = 0; m < 2; ++m) {
            int r = rowBase + warpM * 32 + m * 16 + (lane >> 2);
            loadAfrag(a[m], A, r, kc, IN_DIM, M);
        }
        uint2 b[8];
        #pragma unroll
        for (int n = 0; n < 8; ++n) {
            int n8 = warpN * 8 + n;
            b[n] = g_BfragIn[(size_t)((n8 * 16 + kg) * 32 + lane)];
        }
        #pragma unroll
        for (int m = 0; m < 2; ++m)
            #pragma unroll
            for (int n = 0; n < 8; ++n)
                MMA_F16(c[m][n], a[m], (unsigned*)&b[n]);
    }

    #pragma unroll
    for (int m = 0; m < 2; ++m) {
        int r0 = rowBase + warpM * 32 + m * 16 + (lane >> 2);
        #pragma unroll
        for (int n = 0; n < 8; ++n) {
            int col = warpN * 64 + n * 8 + (lane & 3) * 2;
            float bb0 = bias0[col];
            float bb1 = bias0[col + 1];
            if (r0 < M)
                *(float2*)(C0 + (size_t)r0 * 128 + col) =
                    make_float2(c[m][n][0] + bb0, c[m][n][1] + bb1);
            if (r0 + 8 < M)
                *(float2*)(C0 + (size_t)(r0 + 8) * 128 + col) =
                    make_float2(c[m][n][2] + bb0, c[m][n][3] + bb1);
        }
    }
}

// ---------------- fused layer GEMM (K=128), register-direct ------------------
__global__ __launch_bounds__(256, 2)
void gemm_layer_reg_kernel(const float* __restrict__ A,
                           const uint2* __restrict__ BfragL,  // [2][16][8][32]
                           const float* __restrict__ bias1,
                           __half* __restrict__ C0, float* __restrict__ C1,
                           int M) {
    int tid  = threadIdx.x;
    int lane = tid & 31;
    int warp = tid >> 5;
    int warpM = warp >> 1;
    int warpN = warp & 1;
    int rowBase = blockIdx.x * GBM;

    #pragma unroll
    for (int t = 0; t < 2; ++t) {
        const uint2* Bf = BfragL + (size_t)t * (16 * 8 * 32);
        float c[2][8][4] = {};

        #pragma unroll
        for (int kg = 0; kg < 8; ++kg) {
            int kc = kg * 16 + (lane & 3) * 2;
            unsigned a[2][4];
            #pragma unroll
            for (int m = 0; m < 2; ++m) {
                int r = rowBase + warpM * 32 + m * 16 + (lane >> 2);
                loadAfrag(a[m], A, r, kc, HID, M);
            }
            uint2 b[8];
            #pragma unroll
            for (int n = 0; n < 8; ++n) {
                int n8 = warpN * 8 + n;
                b[n] = Bf[(size_t)((n8 * 8 + kg) * 32 + lane)];
            }
            #pragma unroll
            for (int m = 0; m < 2; ++m)
                #pragma unroll
                for (int n = 0; n < 8; ++n)
                    MMA_F16(c[m][n], a[m], (unsigned*)&b[n]);
        }

        #pragma unroll
        for (int m = 0; m < 2; ++m) {
            int r0 = rowBase + warpM * 32 + m * 16 + (lane >> 2);
            #pragma unroll
            for (int n = 0; n < 8; ++n) {
                int col = warpN * 64 + n * 8 + (lane & 3) * 2;
                if (t == 0) {   // P1 -> fp16, no bias
                    if (r0 < M)
                        *(__half2*)(C0 + (size_t)r0 * 128 + col) =
                            __floats2half2_rn(c[m][n][0], c[m][n][1]);
                    if (r0 + 8 < M)
                        *(__half2*)(C0 + (size_t)(r0 + 8) * 128 + col) =
                            __floats2half2_rn(c[m][n][2], c[m][n][3]);
                } else {        // P2 -> fp32 + bias
                    float bb0 = bias1[col];
                    float bb1 = bias1[col + 1];
                    if (r0 < M)
                        *(float2*)(C1 + (size_t)r0 * 128 + col) =
                            make_float2(c[m][n][0] + bb0, c[m][n][1] + bb1);
                    if (r0 + 8 < M)
                        *(float2*)(C1 + (size_t)(r0 + 8) * 128 + col) =
                            make_float2(c[m][n][2] + bb0, c[m][n][3] + bb1);
                }
            }
        }
    }
}

// ---------------- edge message + aggregation (warp per dst node) -------------
__device__ __forceinline__ float4 h2f4(uint2 raw) {
    __half2 h0 = *reinterpret_cast<__half2*>(&raw.x);
    __half2 h1 = *reinterpret_cast<__half2*>(&raw.y);
    float2 f0 = __half22float2(h0);
    float2 f1 = __half22float2(h1);
    return make_float4(f0.x, f0.y, f1.x, f1.y);
}

#define EDGE_ONE(p1v, eav)                                                        \
    do {                                                                          \
        float mx = (p1v).x + p2.x + (eav).x * w0.x + (eav).y * w1.x +             \
                   (eav).z * w2.x + (eav).w * w3.x;                               \
        float my = (p1v).y + p2.y + (eav).x * w0.y + (eav).y * w1.y +             \
                   (eav).z * w2.y + (eav).w * w3.y;                               \
        float mz = (p1v).z + p2.z + (eav).x * w0.z + (eav).y * w1.z +             \
                   (eav).z * w2.z + (eav).w * w3.z;                               \
        float mw = (p1v).w + p2.w + (eav).x * w0.w + (eav).y * w1.w +             \
                   (eav).z * w2.w + (eav).w * w3.w;                               \
        acc.x += fmaxf(mx, 0.f); acc.y += fmaxf(my, 0.f);                         \
        acc.z += fmaxf(mz, 0.f); acc.w += fmaxf(mw, 0.f);                         \
    } while (0)

// raw-batched accumulation: ALL loads (src, raw P1, ea) issue before any
// convert/FMA consumes them -> true MLP ~12 outstanding loads per warp.
__device__ __forceinline__ float4 edge_accum(const __half* __restrict__ P1,
                                             int c4, int e0, int e1,
                                             float4 p2, float4 w0, float4 w1,
                                             float4 w2, float4 w3) {
    float4 acc = make_float4(0.f, 0.f, 0.f, 0.f);
    int e = e0;
    for (; e + 3 < e1; e += 4) {
        int s0 = __ldg(&g_csr_src[e]);
        int s1 = __ldg(&g_csr_src[e + 1]);
        int s2 = __ldg(&g_csr_src[e + 2]);
        int s3 = __ldg(&g_csr_src[e + 3]);
        uint2 r0 = __ldg((const uint2*)(P1 + (size_t)s0 * HID + c4));
        uint2 r1 = __ldg((const uint2*)(P1 + (size_t)s1 * HID + c4));
        uint2 r2 = __ldg((const uint2*)(P1 + (size_t)s2 * HID + c4));
        uint2 r3 = __ldg((const uint2*)(P1 + (size_t)s3 * HID + c4));
        float4 a0 = g_csr_ea[e];
        float4 a1 = g_csr_ea[e + 1];
        float4 a2 = g_csr_ea[e + 2];
        float4 a3 = g_csr_ea[e + 3];
        // consume (raw uint2 -> float4 conversion happens after all loads issued)
        { float4 q = h2f4(r0); EDGE_ONE(q, a0); }
        { float4 q = h2f4(r1); EDGE_ONE(q, a1); }
        { float4 q = h2f4(r2); EDGE_ONE(q, a2); }
        { float4 q = h2f4(r3); EDGE_ONE(q, a3); }
    }
    for (; e < e1; ++e) {
        int    s  = __ldg(&g_csr_src[e]);
        uint2  r  = __ldg((const uint2*)(P1 + (size_t)s * HID + c4));
        float4 aa = g_csr_ea[e];
        float4 q  = h2f4(r);
        EDGE_ONE(q, aa);
    }
    return acc;
}

__global__ __launch_bounds__(256)
void edge_msg_kernel(const __half* __restrict__ P1, const float* __restrict__ P2,
                     const float* __restrict__ W3 /* [4,128] */) {
    int warp = (blockIdx.x * blockDim.x + threadIdx.x) >> 5;
    int lane = threadIdx.x & 31;
    if (warp >= N_NODES) return;
    int v = warp;
    int c4 = lane * 4;

    float4 w0 = *(const float4*)(W3 + 0 * HID + c4);
    float4 w1 = *(const float4*)(W3 + 1 * HID + c4);
    float4 w2 = *(const float4*)(W3 + 2 * HID + c4);
    float4 w3 = *(const float4*)(W3 + 3 * HID + c4);
    float4 p2 = *(const float4*)(P2 + (size_t)v * HID + c4);

    float4 acc = edge_accum(P1, c4, g_off[v], g_off[v + 1], p2, w0, w1, w2, w3);

    float4 xv = *(float4*)(g_x + (size_t)v * HID + c4);
    xv.x += acc.x; xv.y += acc.y; xv.z += acc.z; xv.w += acc.w;
    *(float4*)(g_x + (size_t)v * HID + c4) = xv;
}

// last layer: fuse output projection; never writes g_x (saves full RW pass)
__global__ __launch_bounds__(256)
void edge_msg_out_kernel(const __half* __restrict__ P1, const float* __restrict__ P2,
                         const float* __restrict__ W3,
                         const float* __restrict__ Wout,
                         const float* __restrict__ bout,
                         float* __restrict__ out) {
    int warp = (blockIdx.x * blockDim.x + threadIdx.x) >> 5;
    int lane = threadIdx.x & 31;
    if (warp >= N_NODES) return;
    int v = warp;
    int c4 = lane * 4;

    float4 w0 = *(const float4*)(W3 + 0 * HID + c4);
    float4 w1 = *(const float4*)(W3 + 1 * HID + c4);
    float4 w2 = *(const float4*)(W3 + 2 * HID + c4);
    float4 w3 = *(const float4*)(W3 + 3 * HID + c4);
    float4 p2 = *(const float4*)(P2 + (size_t)v * HID + c4);

    float4 acc = edge_accum(P1, c4, g_off[v], g_off[v + 1], p2, w0, w1, w2, w3);

    float4 xv = *(float4*)(g_x + (size_t)v * HID + c4);
    xv.x += acc.x; xv.y += acc.y; xv.z += acc.z; xv.w += acc.w;

    // output projection from in-register xv; lane owns dims c4..c4+3
    float s0 = xv.x * Wout[(c4 + 0) * 3 + 0] + xv.y * Wout[(c4 + 1) * 3 + 0]
             + xv.z * Wout[(c4 + 2) * 3 + 0] + xv.w * Wout[(c4 + 3) * 3 + 0];
    float s1 = xv.x * Wout[(c4 + 0) * 3 + 1] + xv.y * Wout[(c4 + 1) * 3 + 1]
             + xv.z * Wout[(c4 + 2) * 3 + 1] + xv.w * Wout[(c4 + 3) * 3 + 1];
    float s2 = xv.x * Wout[(c4 + 0) * 3 + 2] + xv.y * Wout[(c4 + 1) * 3 + 2]
             + xv.z * Wout[(c4 + 2) * 3 + 2] + xv.w * Wout[(c4 + 3) * 3 + 2];
    #pragma unroll
    for (int o = 16; o > 0; o >>= 1) {
        s0 += __shfl_xor_sync(0xFFFFFFFFu, s0, o);
        s1 += __shfl_xor_sync(0xFFFFFFFFu, s1, o);
        s2 += __shfl_xor_sync(0xFFFFFFFFu, s2, o);
    }
    if (lane == 0) {
        out[v * 3 + 0] = s0 + bout[0];
        out[v * 3 + 1] = s1 + bout[1];
        out[v * 3 + 2] = s2 + bout[2];
    }
}

// ---------------- launch ------------------------------------------------------
extern "C" void kernel_launch(void* const* d_in, const int* in_sizes, int n_in,
                              void* d_out, int out_size) {
    const float* h     = (const float*)d_in[0];
    const int*   ei    = (const int*)  d_in[1];
    const float* ea    = (const float*)d_in[2];
    const float* W_in  = (const float*)d_in[3];
    const float* b_in  = (const float*)d_in[4];
    const float* W_msg = (const float*)d_in[5];
    const float* b_msg = (const float*)d_in[6];
    const float* W_out = (const float*)d_in[7];
    const float* b_out = (const float*)d_in[8];
    float* out = (float*)d_out;

    float  *px, *pP2;
    __half *pP1h;
    int    *pdeg;
    uint2  *pBfrag;
    cudaGetSymbolAddress((void**)&px,    g_x);
    cudaGetSymbolAddress((void**)&pP1h,  g_P1h);
    cudaGetSymbolAddress((void**)&pP2,   g_P2);
    cudaGetSymbolAddress((void**)&pdeg,  g_deg);
    cudaGetSymbolAddress((void**)&pBfrag, g_Bfrag);

    cudaMemsetAsync(pdeg, 0, N_NODES * sizeof(int), 0);

    const int EB = (N_EDGES + 255) / 256;
    count_prep_kernel<<<EB, 256>>>(ei, W_in, W_msg);   // count + B-frag prep
    scan_deg_kernel<<<1, 1024>>>();                    // single-block scan
    fill_csr_kernel<<<EB, 256>>>(ei, ea);

    const int MT = (N_NODES + GBM - 1) / GBM;   // 391

    gemm_in_reg_kernel<<<MT, 256>>>(h, b_in, px, N_NODES);   // 4th kernel: profiled

    const int NODE_WARP_BLOCKS = (N_NODES * 32 + 255) / 256;
    for (int l = 0; l < N_LAYERS; ++l) {
        const float* Wl = W_msg + (size_t)l * (2 * HID + EDGE_DIM) * HID;
        gemm_layer_reg_kernel<<<MT, 256>>>(px,
                                           pBfrag + (size_t)l * 2 * 16 * 8 * 32,
                                           b_msg + l * HID,
                                           pP1h, pP2, N_NODES);
        if (l < N_LAYERS - 1) {
            edge_msg_kernel<<<NODE_WARP_BLOCKS, 256>>>(pP1h, pP2,
                                                       Wl + 2 * HID * HID);
        } else {
            edge_msg_out_kernel<<<NODE_WARP_BLOCKS, 256>>>(pP1h, pP2,
                                                           Wl + 2 * HID * HID,
                                                           W_out, b_out, out);
        }
    }
}